// round 11
// baseline (speedup 1.0000x reference)
#include <cuda_runtime.h>
#include <cuda_fp16.h>
#include <cstdint>

#define BATCHN 2
#define SEQ    2048
#define DIM    1024
#define NHEAD  16
#define HDIM   64
#define MTOT   (BATCHN*SEQ)   // 4096
#define NQB2   (SEQ/256)      // 8 attention q-blocks (256 rows each)

// ---------------- scratch (no allocs; raw u16) ----------------
__device__ unsigned short g_q[(size_t)BATCHN*NHEAD*SEQ*HDIM];   // [B,H,S,Hd] f16
__device__ unsigned short g_k[(size_t)BATCHN*NHEAD*SEQ*HDIM];
__device__ unsigned short g_v[(size_t)BATCHN*NHEAD*SEQ*HDIM];
__device__ unsigned short g_ctx[(size_t)MTOT*DIM];              // [B*S, D] f16
__device__ unsigned short g_xr[(size_t)MTOT*DIM];               // input f16
__device__ unsigned short g_wt[(size_t)4*DIM*DIM];              // W^T f16: Wq,Wk,Wv,Wo

// ---------------- helpers (compute_103-baseline PTX only) ----------------
__device__ __forceinline__ uint32_t smem_u32(const void* p) {
    uint32_t a;
    asm("{ .reg .u64 t; cvta.to.shared.u64 t, %1; cvt.u32.u64 %0, t; }" : "=r"(a) : "l"(p));
    return a;
}
__device__ __forceinline__ uint32_t pack_h2(float lo, float hi) {
    __half2 h = __floats2half2_rn(lo, hi);
    return *reinterpret_cast<uint32_t*>(&h);
}
__device__ __forceinline__ void cpasync16(uint32_t dst, const void* src) {
    asm volatile("cp.async.cg.shared.global [%0], [%1], 16;" :: "r"(dst), "l"(src));
}
#define CP_COMMIT() asm volatile("cp.async.commit_group;" ::: "memory")
#define CP_WAIT(n)  asm volatile("cp.async.wait_group %0;" :: "n"(n) : "memory")

__device__ __forceinline__ void ldsm4(uint32_t& r0, uint32_t& r1, uint32_t& r2,
                                      uint32_t& r3, uint32_t a) {
    asm volatile("ldmatrix.sync.aligned.m8n8.x4.shared.b16 {%0,%1,%2,%3}, [%4];"
                 : "=r"(r0), "=r"(r1), "=r"(r2), "=r"(r3) : "r"(a));
}
__device__ __forceinline__ void ldsm4t(uint32_t& r0, uint32_t& r1, uint32_t& r2,
                                       uint32_t& r3, uint32_t a) {
    asm volatile("ldmatrix.sync.aligned.m8n8.x4.trans.shared.b16 {%0,%1,%2,%3}, [%4];"
                 : "=r"(r0), "=r"(r1), "=r"(r2), "=r"(r3) : "r"(a));
}
// D(fp32) += A(f16 m16k16, row) * B(f16 k16n8, col)
__device__ __forceinline__ void mma_f16(float* d, const uint32_t* a, const uint32_t* b) {
    asm volatile("mma.sync.aligned.m16n8k16.row.col.f32.f16.f16.f32 "
                 "{%0,%1,%2,%3}, {%4,%5,%6,%7}, {%8,%9}, {%0,%1,%2,%3};"
                 : "+f"(d[0]), "+f"(d[1]), "+f"(d[2]), "+f"(d[3])
                 : "r"(a[0]), "r"(a[1]), "r"(a[2]), "r"(a[3]), "r"(b[0]), "r"(b[1]));
}

// ---------------------------------------------------------------------------
// prep: z<4 -> W_z^T to f16; z==4 -> input round to f16. One launch.
// ---------------------------------------------------------------------------
__global__ void prep_kernel(const float* __restrict__ x,
                            const float* __restrict__ Wq, const float* __restrict__ Wk,
                            const float* __restrict__ Wv, const float* __restrict__ Wo,
                            unsigned short* __restrict__ xr,
                            unsigned short* __restrict__ Wt) {
    int tx = threadIdx.x, ty = threadIdx.y;
    if (blockIdx.z == 4) {                  // round x -> f16 (4 float4s / thread)
        int bid = blockIdx.y * 32 + blockIdx.x;
        int t = ty * 32 + tx;
        #pragma unroll
        for (int j = 0; j < 4; j++) {
            int i = bid * 1024 + j * 256 + t;
            float4 v = reinterpret_cast<const float4*>(x)[i];
            uint2 o = { pack_h2(v.x, v.y), pack_h2(v.z, v.w) };
            reinterpret_cast<uint2*>(xr)[i] = o;
        }
        return;
    }
    __shared__ float t[32][33];
    int z = blockIdx.z;
    const float* W = (z == 0) ? Wq : (z == 1) ? Wk : (z == 2) ? Wv : Wo;
    unsigned short* dst = Wt + (size_t)z * DIM * DIM;
    int k0 = blockIdx.x * 32, n0 = blockIdx.y * 32;
    #pragma unroll
    for (int i = 0; i < 32; i += 8)
        t[ty + i][tx] = W[(size_t)(k0 + ty + i) * DIM + n0 + tx];
    __syncthreads();
    #pragma unroll
    for (int i = 0; i < 32; i += 8) {
        __half h = __float2half_rn(t[tx][ty + i]);
        dst[(size_t)(n0 + ty + i) * DIM + k0 + tx] = *reinterpret_cast<unsigned short*>(&h);
    }
}

// ---------------------------------------------------------------------------
// GEMM (mma.sync f16, fp32 accum): CTA 128x128, BK=64, 3-stage cp.async.
// 256 thr, 8 warps, warp tile 32x64: wm = wid&3 (m 4x32), wn = wid>>2 (n 2x64).
// acc = 64 regs/thread -> <=128 regs -> 2 CTAs/SM = 4 warps/SMSP (latency
// hiding for the ldsm->mma dependency, the R10 bottleneck).
// smem: stage st at st*32768 (A 16K + B 16K). Total 96KB; 2 CTAs/SM = 192KB.
// MODE 0: out[4096,1024] fp32 row-major. MODE 1: fused QKV (N=3072) f16
//         scatter to [B,H,S,Hd]; segment n0>>10 selects bias/dest.
// ---------------------------------------------------------------------------
#define GEMM_SMEM 98304

template<int MODE>
__global__ void __launch_bounds__(256, 2)
gemm_mma(const unsigned short* __restrict__ A, const unsigned short* __restrict__ Wt,
         const float* __restrict__ b0p, const float* __restrict__ b1p,
         const float* __restrict__ b2p,
         void* __restrict__ o0, void* __restrict__ o1, void* __restrict__ o2)
{
    extern __shared__ char smem[];
    const uint32_t sb = smem_u32(smem);
    const int tid = threadIdx.x, lane = tid & 31, wid = tid >> 5;
    const int wm = wid & 3, wn = wid >> 2;
    const int m0 = blockIdx.y * 128, n0 = blockIdx.x * 128;

    float acc[2][8][4];                     // mt(2 x m16) x nf(8 x n8)
    #pragma unroll
    for (int i = 0; i < 2; i++)
        #pragma unroll
        for (int j = 0; j < 8; j++)
            #pragma unroll
            for (int r = 0; r < 4; r++) acc[i][j][r] = 0.0f;

    auto load_chunk = [&](int st, int k0) {
        uint32_t ab = sb + st * 32768, bb = ab + 16384;
        #pragma unroll
        for (int i = 0; i < 4; i++) {       // A: 128 rows x 8 quads (8 halves ea)
            int idx = tid + i * 256, r = idx >> 3, c = idx & 7;
            cpasync16(ab + r * 128 + 16 * (c ^ (r & 7)),
                      A + (size_t)(m0 + r) * DIM + k0 + c * 8);
        }
        #pragma unroll
        for (int i = 0; i < 4; i++) {       // B (Wt): 128 n-rows x 8 quads
            int idx = tid + i * 256, r = idx >> 3, c = idx & 7;
            cpasync16(bb + r * 128 + 16 * (c ^ (r & 7)),
                      Wt + (size_t)(n0 + r) * DIM + k0 + c * 8);
        }
        CP_COMMIT();
    };

    load_chunk(0, 0);
    load_chunk(1, 64);
    for (int ch = 0; ch < 16; ch++) {       // BK=64, K=1024
        int st = ch % 3;
        if (ch + 1 < 16) CP_WAIT(1); else CP_WAIT(0);
        __syncthreads();                    // chunk ch visible; ch-1 consumed
        if (ch + 2 < 16) load_chunk((ch + 2) % 3, (ch + 2) * 64);

        uint32_t ab = sb + st * 32768, bb = ab + 16384;
        #pragma unroll
        for (int ks = 0; ks < 4; ks++) {    // 4 x k16
            uint32_t a[2][4], b[4][4];
            #pragma unroll
            for (int mt = 0; mt < 2; mt++) {
                int row = wm * 32 + mt * 16 + (lane & 15);
                int at  = 2 * ks + (lane >> 4);
                ldsm4(a[mt][0], a[mt][1], a[mt][2], a[mt][3],
                      ab + row * 128 + 16 * (at ^ (row & 7)));
            }
            #pragma unroll
            for (int pr = 0; pr < 4; pr++) {
                int row = wn * 64 + pr * 16 + (lane & 7) + ((lane & 16) ? 8 : 0);
                int at  = 2 * ks + ((lane >> 3) & 1);
                ldsm4(b[pr][0], b[pr][1], b[pr][2], b[pr][3],
                      bb + row * 128 + 16 * (at ^ (row & 7)));
            }
            #pragma unroll
            for (int mt = 0; mt < 2; mt++)
                #pragma unroll
                for (int pr = 0; pr < 4; pr++) {
                    mma_f16(acc[mt][2 * pr],     a[mt], &b[pr][0]);
                    mma_f16(acc[mt][2 * pr + 1], a[mt], &b[pr][2]);
                }
        }
    }

    // epilogue
    const float* bias;
    unsigned short* outh = nullptr;
    float* outf = nullptr;
    if (MODE == 0) { bias = b0p; outf = (float*)o0; }
    else {
        int seg = n0 >> 10;
        bias = (seg == 0) ? b0p : (seg == 1) ? b1p : b2p;
        outh = (unsigned short*)((seg == 0) ? o0 : (seg == 1) ? o1 : o2);
    }
    const int rb = m0 + wm * 32 + (lane >> 2);
    const int cb = (MODE == 0 ? n0 : (n0 & 1023)) + wn * 64 + 2 * (lane & 3);
    #pragma unroll
    for (int mt = 0; mt < 2; mt++) {
        #pragma unroll
        for (int nf = 0; nf < 8; nf++) {
            int r = rb + mt * 16, c = cb + nf * 8;
            float b0 = bias[c], b1 = bias[c + 1];
            float x0 = acc[mt][nf][0] + b0, x1 = acc[mt][nf][1] + b1;
            float x2 = acc[mt][nf][2] + b0, x3 = acc[mt][nf][3] + b1;
            if (MODE == 0) {
                float2 v0 = {x0, x1}, v1 = {x2, x3};
                *reinterpret_cast<float2*>(outf + (size_t)r * DIM + c) = v0;
                *reinterpret_cast<float2*>(outf + (size_t)(r + 8) * DIM + c) = v1;
            } else {
                int bt = r >> 11, h = c >> 6, hd = c & 63;
                size_t base = (((size_t)(bt * NHEAD + h)) * SEQ) * HDIM + hd;
                *reinterpret_cast<uint32_t*>(outh + base + (size_t)(r & 2047) * HDIM) =
                    pack_h2(x0, x1);
                *reinterpret_cast<uint32_t*>(outh + base + (size_t)((r + 8) & 2047) * HDIM) =
                    pack_h2(x2, x3);
            }
        }
    }
}

// ---------------------------------------------------------------------------
// Flash attention (mma.sync f16, static-max softmax, causal-paired CTAs).
// CTA = 256 q-rows: 256 threads, 8 warps x m32. kv tiles 64; 4-stage cp.async.
// CTA bx handles q-blocks {bx, NQB2-1-bx}; warps skip fully-masked kv-tiles.
// smem: stage st -> K at st*16K, V at +8K. 64KB; 1 CTA/SM. (unchanged)
// ---------------------------------------------------------------------------
#define ATTN_SMEM 65536

__global__ void __launch_bounds__(256, 1)
flash_attn_mma(const unsigned short* __restrict__ gq,
               const unsigned short* __restrict__ gk,
               const unsigned short* __restrict__ gv,
               unsigned short* __restrict__ ctx)
{
    extern __shared__ char smem[];
    const uint32_t sb = smem_u32(smem);
    const int tid = threadIdx.x, lane = tid & 31, wid = tid >> 5;
    const int bh = blockIdx.y, b = bh >> 4, h = bh & 15;

    const unsigned short* kbase = gk + (size_t)bh * SEQ * HDIM;
    const unsigned short* vbase = gv + (size_t)bh * SEQ * HDIM;

    const __half2 c_sc2   = __float2half2_rn(0.18033688011112042f);  // (1/8)*log2(e)
    const __half2 c_negM  = __float2half2_rn(-6.0f);
    const __half2 c_clamp = __float2half2_rn(15.0f);
    uint32_t ones2[2];
    ones2[0] = (lane < 4) ? 0x3C003C00u : 0u;   // col 0 of n8 block = 1.0
    ones2[1] = ones2[0];

    auto p_of = [&](uint32_t packed_sc) -> uint32_t {
        __half2 u = *reinterpret_cast<__half2*>(&packed_sc);
        __half2 y = __hmin2(__hfma2(u, c_sc2, c_negM), c_clamp);
        uint32_t r;
        asm("ex2.approx.f16x2 %0, %1;" : "=r"(r) : "r"(*reinterpret_cast<uint32_t*>(&y)));
        return r;
    };

    auto loadKV = [&](int t, int st) {      // K + V: 64 rows x 8 quads each
        uint32_t kb = sb + st * 16384, vb = kb + 8192;
        #pragma unroll
        for (int i = 0; i < 2; i++) {
            int idx = tid + i * 256, r = idx >> 3, c = idx & 7;
            uint32_t off = r * 128 + 16 * (c ^ (r & 7));
            const unsigned short* s = kbase + (size_t)(t * 64 + r) * 64 + c * 8;
            cpasync16(kb + off, s);
            cpasync16(vb + off, vbase + (s - kbase));
        }
        CP_COMMIT();
    };

    #pragma unroll 1
    for (int pass = 0; pass < 2; pass++) {
        const int qb = pass ? (NQB2 - 1 - blockIdx.x) : blockIdx.x;
        const int nt_tiles = 4 * qb + 4;
        const unsigned short* qg =
            gq + ((size_t)bh * SEQ + qb * 256 + wid * 32) * HDIM;

        uint32_t qf[2][4][4];
        {
            int r = lane >> 2, c2 = 2 * (lane & 3);
            #pragma unroll
            for (int hf = 0; hf < 2; hf++) {
                const unsigned short* qh = qg + hf * 16 * HDIM;
                #pragma unroll
                for (int ks = 0; ks < 4; ks++) {
                    qf[hf][ks][0] = *reinterpret_cast<const uint32_t*>(qh + r * 64 + ks * 16 + c2);
                    qf[hf][ks][1] = *reinterpret_cast<const uint32_t*>(qh + (r + 8) * 64 + ks * 16 + c2);
                    qf[hf][ks][2] = *reinterpret_cast<const uint32_t*>(qh + r * 64 + ks * 16 + 8 + c2);
                    qf[hf][ks][3] = *reinterpret_cast<const uint32_t*>(qh + (r + 8) * 64 + ks * 16 + 8 + c2);
                }
            }
        }

        float O[2][8][4];
        #pragma unroll
        for (int hf = 0; hf < 2; hf++)
            #pragma unroll
            for (int i = 0; i < 8; i++)
                #pragma unroll
                for (int j = 0; j < 4; j++) O[hf][i][j] = 0.0f;
        float Ol[2][4] = {{0,0,0,0},{0,0,0,0}};

        __syncthreads();
        loadKV(0, 0);
        loadKV(1, 1);
        loadKV(2, 2);

        const int row0g = qb * 256 + wid * 32 + (lane >> 2);

        for (int t = 0; t < nt_tiles; t++) {
            int st = t & 3;
            if (t + 2 < nt_tiles)      CP_WAIT(2);
            else if (t + 1 < nt_tiles) CP_WAIT(1);
            else                       CP_WAIT(0);
            __syncthreads();
            if (t + 3 < nt_tiles) loadKV(t + 3, (t + 3) & 3);

            const bool diag = (t >= 4 * qb);
            const int  tl   = t - 4 * qb;
            if (diag && tl * 64 > wid * 32 + 31) continue;   // P == 0, skip

            float sc[2][8][4];
            #pragma unroll
            for (int hf = 0; hf < 2; hf++)
                #pragma unroll
                for (int i = 0; i < 8; i++)
                    #pragma unroll
                    for (int j = 0; j < 4; j++) sc[hf][i][j] = 0.0f;

            uint32_t kb = sb + st * 16384;
            #pragma unroll
            for (int ks = 0; ks < 4; ks++) {
                #pragma unroll
                for (int pr = 0; pr < 4; pr++) {
                    int row = pr * 16 + (lane & 7) + ((lane & 16) ? 8 : 0);
                    int at  = 2 * ks + ((lane >> 3) & 1);
                    uint32_t bfr[4];
                    ldsm4(bfr[0], bfr[1], bfr[2], bfr[3],
                          kb + row * 128 + 16 * (at ^ (row & 7)));
                    #pragma unroll
                    for (int hf = 0; hf < 2; hf++) {
                        mma_f16(sc[hf][2 * pr],     qf[hf][ks], &bfr[0]);
                        mma_f16(sc[hf][2 * pr + 1], qf[hf][ks], &bfr[2]);
                    }
                }
            }

            if (diag && tl * 64 + 63 > wid * 32) {
                #pragma unroll
                for (int hf = 0; hf < 2; hf++)
                    #pragma unroll
                    for (int nt = 0; nt < 8; nt++)
                        #pragma unroll
                        for (int j = 0; j < 4; j++) {
                            int col = t * 64 + nt * 8 + 2 * (lane & 3) + (j & 1);
                            int row = row0g + hf * 16 + ((j >> 1) << 3);
                            if (col > row) sc[hf][nt][j] = -1e30f;
                        }
            }

            uint32_t vb = sb + st * 16384 + 8192;
            #pragma unroll
            for (int ks = 0; ks < 4; ks++) {
                uint32_t pa[2][4];
                #pragma unroll
                for (int hf = 0; hf < 2; hf++) {
                    pa[hf][0] = p_of(pack_h2(sc[hf][2 * ks][0],     sc[hf][2 * ks][1]));
                    pa[hf][1] = p_of(pack_h2(sc[hf][2 * ks][2],     sc[hf][2 * ks][3]));
                    pa[hf][2] = p_of(pack_h2(sc[hf][2 * ks + 1][0], sc[hf][2 * ks + 1][1]));
                    pa[hf][3] = p_of(pack_h2(sc[hf][2 * ks + 1][2], sc[hf][2 * ks + 1][3]));
                    mma_f16(Ol[hf], pa[hf], ones2);
                }
                #pragma unroll
                for (int hp = 0; hp < 4; hp++) {
                    int kv = ks * 16 + (lane & 7) + (((lane >> 3) & 1) ? 8 : 0);
                    int q  = 2 * hp + ((lane >> 4) & 1);
                    uint32_t bfr[4];
                    ldsm4t(bfr[0], bfr[1], bfr[2], bfr[3],
                           vb + kv * 128 + 16 * (q ^ (kv & 7)));
                    #pragma unroll
                    for (int hf = 0; hf < 2; hf++) {
                        mma_f16(O[hf][2 * hp],     pa[hf], &bfr[0]);
                        mma_f16(O[hf][2 * hp + 1], pa[hf], &bfr[2]);
                    }
                }
            }
        }

        #pragma unroll
        for (int hf = 0; hf < 2; hf++) {
            float l0 = __shfl_sync(0xffffffffu, Ol[hf][0], lane & 0x1C);
            float l1 = __shfl_sync(0xffffffffu, Ol[hf][2], lane & 0x1C);
            float inv0 = 1.0f / l0, inv1 = 1.0f / l1;
            unsigned short* cb0 = ctx + ((size_t)b * SEQ + row0g + hf * 16) * DIM
                                  + h * 64 + 2 * (lane & 3);
            #pragma unroll
            for (int nt = 0; nt < 8; nt++) {
                *reinterpret_cast<uint32_t*>(cb0 + nt * 8) =
                    pack_h2(O[hf][nt][0] * inv0, O[hf][nt][1] * inv0);
                *reinterpret_cast<uint32_t*>(cb0 + (size_t)8 * DIM + nt * 8) =
                    pack_h2(O[hf][nt][2] * inv1, O[hf][nt][3] * inv1);
            }
        }
    }
}

// ---------------------------------------------------------------------------
extern "C" void kernel_launch(void* const* d_in, const int* in_sizes, int n_in,
                              void* d_out, int out_size)
{
    const float* x  = (const float*)d_in[0];
    const float* Wq = (const float*)d_in[1];
    const float* bq = (const float*)d_in[2];
    const float* Wk = (const float*)d_in[3];
    const float* bk = (const float*)d_in[4];
    const float* Wv = (const float*)d_in[5];
    const float* bv = (const float*)d_in[6];
    const float* Wo = (const float*)d_in[7];
    const float* bo = (const float*)d_in[8];
    float* out = (float*)d_out;

    unsigned short *q, *k, *v, *ctx, *xr, *wt;
    cudaGetSymbolAddress((void**)&q,   g_q);
    cudaGetSymbolAddress((void**)&k,   g_k);
    cudaGetSymbolAddress((void**)&v,   g_v);
    cudaGetSymbolAddress((void**)&ctx, g_ctx);
    cudaGetSymbolAddress((void**)&xr,  g_xr);
    cudaGetSymbolAddress((void**)&wt,  g_wt);

    cudaFuncSetAttribute(gemm_mma<0>, cudaFuncAttributeMaxDynamicSharedMemorySize, GEMM_SMEM);
    cudaFuncSetAttribute(gemm_mma<1>, cudaFuncAttributeMaxDynamicSharedMemorySize, GEMM_SMEM);
    cudaFuncSetAttribute(flash_attn_mma, cudaFuncAttributeMaxDynamicSharedMemorySize, ATTN_SMEM);

    // 1. prep: input->f16 + all four W^T (one launch)
    dim3 gp(32, 32, 5), bp(32, 8);
    prep_kernel<<<gp, bp>>>(x, Wq, Wk, Wv, Wo, xr, wt);
    // 2. fused QKV projection (N = 3072), CTA 128x128, 2 CTAs/SM
    dim3 gqkv(3 * DIM / 128, MTOT / 128);   // (24, 32)
    gemm_mma<1><<<gqkv, 256, GEMM_SMEM>>>(xr, wt, bq, bk, bv, q, k, v);
    // 3. attention (256-row CTAs, paired causal blocks)
    dim3 ga(NQB2 / 2, BATCHN * NHEAD);      // (4, 32)
    flash_attn_mma<<<ga, 256, ATTN_SMEM>>>(q, k, v, ctx);
    // 4. output projection
    dim3 go(DIM / 128, MTOT / 128);         // (8, 32)
    gemm_mma<0><<<go, 256, GEMM_SMEM>>>(ctx, wt + (size_t)3 * DIM * DIM,
                                        bo, nullptr, nullptr, out, nullptr, nullptr);
}

// round 14
// speedup vs baseline: 1.0065x; 1.0065x over previous
#include <cuda_runtime.h>
#include <cuda_fp16.h>
#include <cstdint>

#define BATCHN 2
#define SEQ    2048
#define DIM    1024
#define NHEAD  16
#define HDIM   64
#define MTOT   (BATCHN*SEQ)   // 4096
#define NQB2   (SEQ/256)      // 8 attention q-blocks (256 rows each)

// ---------------- scratch (no allocs; raw u16) ----------------
__device__ unsigned short g_q[(size_t)BATCHN*NHEAD*SEQ*HDIM];   // [B,H,S,Hd] f16
__device__ unsigned short g_k[(size_t)BATCHN*NHEAD*SEQ*HDIM];
__device__ unsigned short g_v[(size_t)BATCHN*NHEAD*SEQ*HDIM];
__device__ unsigned short g_ctx[(size_t)MTOT*DIM];              // [B*S, D] f16
__device__ unsigned short g_xr[(size_t)MTOT*DIM];               // input f16
__device__ unsigned short g_wt[(size_t)4*DIM*DIM];              // W^T f16: Wq,Wk,Wv,Wo

// ---------------- helpers (compute_103-baseline PTX only) ----------------
__device__ __forceinline__ uint32_t smem_u32(const void* p) {
    uint32_t a;
    asm("{ .reg .u64 t; cvta.to.shared.u64 t, %1; cvt.u32.u64 %0, t; }" : "=r"(a) : "l"(p));
    return a;
}
__device__ __forceinline__ uint32_t pack_h2(float lo, float hi) {
    __half2 h = __floats2half2_rn(lo, hi);
    return *reinterpret_cast<uint32_t*>(&h);
}
__device__ __forceinline__ void cpasync16(uint32_t dst, const void* src) {
    asm volatile("cp.async.cg.shared.global [%0], [%1], 16;" :: "r"(dst), "l"(src));
}
#define CP_COMMIT() asm volatile("cp.async.commit_group;" ::: "memory")
#define CP_WAIT(n)  asm volatile("cp.async.wait_group %0;" :: "n"(n) : "memory")

__device__ __forceinline__ void ldsm4(uint32_t& r0, uint32_t& r1, uint32_t& r2,
                                      uint32_t& r3, uint32_t a) {
    asm volatile("ldmatrix.sync.aligned.m8n8.x4.shared.b16 {%0,%1,%2,%3}, [%4];"
                 : "=r"(r0), "=r"(r1), "=r"(r2), "=r"(r3) : "r"(a));
}
__device__ __forceinline__ void ldsm4t(uint32_t& r0, uint32_t& r1, uint32_t& r2,
                                       uint32_t& r3, uint32_t a) {
    asm volatile("ldmatrix.sync.aligned.m8n8.x4.trans.shared.b16 {%0,%1,%2,%3}, [%4];"
                 : "=r"(r0), "=r"(r1), "=r"(r2), "=r"(r3) : "r"(a));
}
// D(fp32) += A(f16 m16k16, row) * B(f16 k16n8, col)
__device__ __forceinline__ void mma_f16(float* d, const uint32_t* a, const uint32_t* b) {
    asm volatile("mma.sync.aligned.m16n8k16.row.col.f32.f16.f16.f32 "
                 "{%0,%1,%2,%3}, {%4,%5,%6,%7}, {%8,%9}, {%0,%1,%2,%3};"
                 : "+f"(d[0]), "+f"(d[1]), "+f"(d[2]), "+f"(d[3])
                 : "r"(a[0]), "r"(a[1]), "r"(a[2]), "r"(a[3]), "r"(b[0]), "r"(b[1]));
}

// ---------------------------------------------------------------------------
// prep: z<4 -> W_z^T to f16; z==4 -> input round to f16. One launch.
// ---------------------------------------------------------------------------
__global__ void prep_kernel(const float* __restrict__ x,
                            const float* __restrict__ Wq, const float* __restrict__ Wk,
                            const float* __restrict__ Wv, const float* __restrict__ Wo,
                            unsigned short* __restrict__ xr,
                            unsigned short* __restrict__ Wt) {
    int tx = threadIdx.x, ty = threadIdx.y;
    if (blockIdx.z == 4) {                  // round x -> f16 (4 float4s / thread)
        int bid = blockIdx.y * 32 + blockIdx.x;
        int t = ty * 32 + tx;
        #pragma unroll
        for (int j = 0; j < 4; j++) {
            int i = bid * 1024 + j * 256 + t;
            float4 v = reinterpret_cast<const float4*>(x)[i];
            uint2 o = { pack_h2(v.x, v.y), pack_h2(v.z, v.w) };
            reinterpret_cast<uint2*>(xr)[i] = o;
        }
        return;
    }
    __shared__ float t[32][33];
    int z = blockIdx.z;
    const float* W = (z == 0) ? Wq : (z == 1) ? Wk : (z == 2) ? Wv : Wo;
    unsigned short* dst = Wt + (size_t)z * DIM * DIM;
    int k0 = blockIdx.x * 32, n0 = blockIdx.y * 32;
    #pragma unroll
    for (int i = 0; i < 32; i += 8)
        t[ty + i][tx] = W[(size_t)(k0 + ty + i) * DIM + n0 + tx];
    __syncthreads();
    #pragma unroll
    for (int i = 0; i < 32; i += 8) {
        __half h = __float2half_rn(t[tx][ty + i]);
        dst[(size_t)(n0 + ty + i) * DIM + k0 + tx] = *reinterpret_cast<unsigned short*>(&h);
    }
}

// ---------------------------------------------------------------------------
// GEMM (mma.sync f16, fp32 accum): CTA 256x128, BK=128, 2-stage cp.async.
// 256 thr, 8 warps (wm = wid>>1 over m 4x64, wn = wid&1 over n 2x64).
// Fragment SOFTWARE PIPELINE: A and B ldsm frags for ks+1 load into alternate
// buffers while ks's 32-mma burst executes -> ldsm latency hidden.
// smem: stage st at st*98304: A 64KB (two 32KB column-halves), B 32KB. 192KB.
// MODE 0: out[4096,1024] fp32 row-major. MODE 1: fused QKV (N=3072) f16
//         scatter to [B,H,S,Hd]; segment n0>>10 selects bias/dest.
// ---------------------------------------------------------------------------
#define GEMM_SMEM 196608

template<int MODE>
__global__ void __launch_bounds__(256, 1)
gemm_mma(const unsigned short* __restrict__ A, const unsigned short* __restrict__ Wt,
         const float* __restrict__ b0p, const float* __restrict__ b1p,
         const float* __restrict__ b2p,
         void* __restrict__ o0, void* __restrict__ o1, void* __restrict__ o2)
{
    extern __shared__ char smem[];
    const uint32_t sb = smem_u32(smem);
    const int tid = threadIdx.x, lane = tid & 31, wid = tid >> 5;
    const int wm = wid >> 1, wn = wid & 1;
    const int m0 = blockIdx.y * 256, n0 = blockIdx.x * 128;

    float acc[4][8][4];                     // mt(4 x m16) x nf(8 x n8)
    #pragma unroll
    for (int i = 0; i < 4; i++)
        #pragma unroll
        for (int j = 0; j < 8; j++)
            #pragma unroll
            for (int r = 0; r < 4; r++) acc[i][j][r] = 0.0f;

    auto load_chunk = [&](int st, int k0) {
        uint32_t ab = sb + st * 98304, bb = ab + 65536;
        #pragma unroll
        for (int i = 0; i < 16; i++) {      // A: 256 rows x 16 quads (8 halves)
            int idx = tid + i * 256, r = idx >> 4, c = idx & 15;
            cpasync16(ab + (c >> 3) * 32768 + r * 128 + 16 * ((c & 7) ^ (r & 7)),
                      A + (size_t)(m0 + r) * DIM + k0 + c * 8);
        }
        #pragma unroll
        for (int i = 0; i < 8; i++) {       // B (Wt): 128 n-rows x 16 quads
            int idx = tid + i * 256, r = idx >> 4, c = idx & 15;
            cpasync16(bb + (c >> 3) * 16384 + r * 128 + 16 * ((c & 7) ^ (r & 7)),
                      Wt + (size_t)(n0 + r) * DIM + k0 + c * 8);
        }
        CP_COMMIT();
    };

    load_chunk(0, 0);
    for (int ch = 0; ch < 8; ch++) {        // BK=128, K=1024
        int st = ch & 1;
        __syncthreads();                    // all warps done with stage st^1
        if (ch + 1 < 8) { load_chunk(st ^ 1, (ch + 1) * 128); CP_WAIT(1); }
        else            { CP_WAIT(0); }
        __syncthreads();                    // chunk ch visible CTA-wide

        uint32_t ab = sb + st * 98304, bb = ab + 65536;
        uint32_t af[2][4][4], bf[2][4][4];  // double-buffered fragments

        auto loadA = [&](int ks, uint32_t (*a)[4]) {
            #pragma unroll
            for (int mt = 0; mt < 4; mt++) {
                int row = wm * 64 + mt * 16 + (lane & 15);
                int at  = 2 * ks + (lane >> 4);
                ldsm4(a[mt][0], a[mt][1], a[mt][2], a[mt][3],
                      ab + (at >> 3) * 32768 + row * 128 + 16 * ((at & 7) ^ (row & 7)));
            }
        };
        auto loadB = [&](int ks, uint32_t (*b)[4]) {
            #pragma unroll
            for (int pr = 0; pr < 4; pr++) {
                int row = wn * 64 + pr * 16 + (lane & 7) + ((lane & 16) ? 8 : 0);
                int at  = 2 * ks + ((lane >> 3) & 1);
                ldsm4(b[pr][0], b[pr][1], b[pr][2], b[pr][3],
                      bb + (at >> 3) * 16384 + row * 128 + 16 * ((at & 7) ^ (row & 7)));
            }
        };

        loadA(0, af[0]);
        loadB(0, bf[0]);
        #pragma unroll
        for (int ks = 0; ks < 8; ks++) {    // 8 x k16, frags one step ahead
            int cur = ks & 1;
            if (ks + 1 < 8) {
                loadA(ks + 1, af[cur ^ 1]);
                loadB(ks + 1, bf[cur ^ 1]);
            }
            #pragma unroll
            for (int mt = 0; mt < 4; mt++)
                #pragma unroll
                for (int pr = 0; pr < 4; pr++) {
                    mma_f16(acc[mt][2 * pr],     af[cur][mt], &bf[cur][pr][0]);
                    mma_f16(acc[mt][2 * pr + 1], af[cur][mt], &bf[cur][pr][2]);
                }
        }
    }

    // epilogue
    const float* bias;
    unsigned short* outh = nullptr;
    float* outf = nullptr;
    if (MODE == 0) { bias = b0p; outf = (float*)o0; }
    else {
        int seg = n0 >> 10;
        bias = (seg == 0) ? b0p : (seg == 1) ? b1p : b2p;
        outh = (unsigned short*)((seg == 0) ? o0 : (seg == 1) ? o1 : o2);
    }
    const int rb = m0 + wm * 64 + (lane >> 2);
    const int cb = (MODE == 0 ? n0 : (n0 & 1023)) + wn * 64 + 2 * (lane & 3);
    #pragma unroll
    for (int mt = 0; mt < 4; mt++) {
        #pragma unroll
        for (int nf = 0; nf < 8; nf++) {
            int r = rb + mt * 16, c = cb + nf * 8;
            float b0 = bias[c], b1 = bias[c + 1];
            float x0 = acc[mt][nf][0] + b0, x1 = acc[mt][nf][1] + b1;
            float x2 = acc[mt][nf][2] + b0, x3 = acc[mt][nf][3] + b1;
            if (MODE == 0) {
                float2 v0 = {x0, x1}, v1 = {x2, x3};
                *reinterpret_cast<float2*>(outf + (size_t)r * DIM + c) = v0;
                *reinterpret_cast<float2*>(outf + (size_t)(r + 8) * DIM + c) = v1;
            } else {
                int bt = r >> 11, h = c >> 6, hd = c & 63;
                size_t base = (((size_t)(bt * NHEAD + h)) * SEQ) * HDIM + hd;
                *reinterpret_cast<uint32_t*>(outh + base + (size_t)(r & 2047) * HDIM) =
                    pack_h2(x0, x1);
                *reinterpret_cast<uint32_t*>(outh + base + (size_t)((r + 8) & 2047) * HDIM) =
                    pack_h2(x2, x3);
            }
        }
    }
}

// ---------------------------------------------------------------------------
// Flash attention (mma.sync f16, static-max softmax, causal-paired CTAs).
// CTA = 256 q-rows: 256 threads, 8 warps x m32. kv tiles 64; 4-stage cp.async.
// CTA bx handles q-blocks {bx, NQB2-1-bx}; warps skip fully-masked kv-tiles.
// smem: stage st -> K at st*16K, V at +8K. 64KB; 1 CTA/SM. (unchanged)
// ---------------------------------------------------------------------------
#define ATTN_SMEM 65536

__global__ void __launch_bounds__(256, 1)
flash_attn_mma(const unsigned short* __restrict__ gq,
               const unsigned short* __restrict__ gk,
               const unsigned short* __restrict__ gv,
               unsigned short* __restrict__ ctx)
{
    extern __shared__ char smem[];
    const uint32_t sb = smem_u32(smem);
    const int tid = threadIdx.x, lane = tid & 31, wid = tid >> 5;
    const int bh = blockIdx.y, b = bh >> 4, h = bh & 15;

    const unsigned short* kbase = gk + (size_t)bh * SEQ * HDIM;
    const unsigned short* vbase = gv + (size_t)bh * SEQ * HDIM;

    const __half2 c_sc2   = __float2half2_rn(0.18033688011112042f);  // (1/8)*log2(e)
    const __half2 c_negM  = __float2half2_rn(-6.0f);
    const __half2 c_clamp = __float2half2_rn(15.0f);
    uint32_t ones2[2];
    ones2[0] = (lane < 4) ? 0x3C003C00u : 0u;   // col 0 of n8 block = 1.0
    ones2[1] = ones2[0];

    auto p_of = [&](uint32_t packed_sc) -> uint32_t {
        __half2 u = *reinterpret_cast<__half2*>(&packed_sc);
        __half2 y = __hmin2(__hfma2(u, c_sc2, c_negM), c_clamp);
        uint32_t r;
        asm("ex2.approx.f16x2 %0, %1;" : "=r"(r) : "r"(*reinterpret_cast<uint32_t*>(&y)));
        return r;
    };

    auto loadKV = [&](int t, int st) {      // K + V: 64 rows x 8 quads each
        uint32_t kb = sb + st * 16384, vb = kb + 8192;
        #pragma unroll
        for (int i = 0; i < 2; i++) {
            int idx = tid + i * 256, r = idx >> 3, c = idx & 7;
            uint32_t off = r * 128 + 16 * (c ^ (r & 7));
            const unsigned short* s = kbase + (size_t)(t * 64 + r) * 64 + c * 8;
            cpasync16(kb + off, s);
            cpasync16(vb + off, vbase + (s - kbase));
        }
        CP_COMMIT();
    };

    #pragma unroll 1
    for (int pass = 0; pass < 2; pass++) {
        const int qb = pass ? (NQB2 - 1 - blockIdx.x) : blockIdx.x;
        const int nt_tiles = 4 * qb + 4;
        const unsigned short* qg =
            gq + ((size_t)bh * SEQ + qb * 256 + wid * 32) * HDIM;

        uint32_t qf[2][4][4];
        {
            int r = lane >> 2, c2 = 2 * (lane & 3);
            #pragma unroll
            for (int hf = 0; hf < 2; hf++) {
                const unsigned short* qh = qg + hf * 16 * HDIM;
                #pragma unroll
                for (int ks = 0; ks < 4; ks++) {
                    qf[hf][ks][0] = *reinterpret_cast<const uint32_t*>(qh + r * 64 + ks * 16 + c2);
                    qf[hf][ks][1] = *reinterpret_cast<const uint32_t*>(qh + (r + 8) * 64 + ks * 16 + c2);
                    qf[hf][ks][2] = *reinterpret_cast<const uint32_t*>(qh + r * 64 + ks * 16 + 8 + c2);
                    qf[hf][ks][3] = *reinterpret_cast<const uint32_t*>(qh + (r + 8) * 64 + ks * 16 + 8 + c2);
                }
            }
        }

        float O[2][8][4];
        #pragma unroll
        for (int hf = 0; hf < 2; hf++)
            #pragma unroll
            for (int i = 0; i < 8; i++)
                #pragma unroll
                for (int j = 0; j < 4; j++) O[hf][i][j] = 0.0f;
        float Ol[2][4] = {{0,0,0,0},{0,0,0,0}};

        __syncthreads();
        loadKV(0, 0);
        loadKV(1, 1);
        loadKV(2, 2);

        const int row0g = qb * 256 + wid * 32 + (lane >> 2);

        for (int t = 0; t < nt_tiles; t++) {
            int st = t & 3;
            if (t + 2 < nt_tiles)      CP_WAIT(2);
            else if (t + 1 < nt_tiles) CP_WAIT(1);
            else                       CP_WAIT(0);
            __syncthreads();
            if (t + 3 < nt_tiles) loadKV(t + 3, (t + 3) & 3);

            const bool diag = (t >= 4 * qb);
            const int  tl   = t - 4 * qb;
            if (diag && tl * 64 > wid * 32 + 31) continue;   // P == 0, skip

            float sc[2][8][4];
            #pragma unroll
            for (int hf = 0; hf < 2; hf++)
                #pragma unroll
                for (int i = 0; i < 8; i++)
                    #pragma unroll
                    for (int j = 0; j < 4; j++) sc[hf][i][j] = 0.0f;

            uint32_t kb = sb + st * 16384;
            #pragma unroll
            for (int ks = 0; ks < 4; ks++) {
                #pragma unroll
                for (int pr = 0; pr < 4; pr++) {
                    int row = pr * 16 + (lane & 7) + ((lane & 16) ? 8 : 0);
                    int at  = 2 * ks + ((lane >> 3) & 1);
                    uint32_t bfr[4];
                    ldsm4(bfr[0], bfr[1], bfr[2], bfr[3],
                          kb + row * 128 + 16 * (at ^ (row & 7)));
                    #pragma unroll
                    for (int hf = 0; hf < 2; hf++) {
                        mma_f16(sc[hf][2 * pr],     qf[hf][ks], &bfr[0]);
                        mma_f16(sc[hf][2 * pr + 1], qf[hf][ks], &bfr[2]);
                    }
                }
            }

            if (diag && tl * 64 + 63 > wid * 32) {
                #pragma unroll
                for (int hf = 0; hf < 2; hf++)
                    #pragma unroll
                    for (int nt = 0; nt < 8; nt++)
                        #pragma unroll
                        for (int j = 0; j < 4; j++) {
                            int col = t * 64 + nt * 8 + 2 * (lane & 3) + (j & 1);
                            int row = row0g + hf * 16 + ((j >> 1) << 3);
                            if (col > row) sc[hf][nt][j] = -1e30f;
                        }
            }

            uint32_t vb = sb + st * 16384 + 8192;
            #pragma unroll
            for (int ks = 0; ks < 4; ks++) {
                uint32_t pa[2][4];
                #pragma unroll
                for (int hf = 0; hf < 2; hf++) {
                    pa[hf][0] = p_of(pack_h2(sc[hf][2 * ks][0],     sc[hf][2 * ks][1]));
                    pa[hf][1] = p_of(pack_h2(sc[hf][2 * ks][2],     sc[hf][2 * ks][3]));
                    pa[hf][2] = p_of(pack_h2(sc[hf][2 * ks + 1][0], sc[hf][2 * ks + 1][1]));
                    pa[hf][3] = p_of(pack_h2(sc[hf][2 * ks + 1][2], sc[hf][2 * ks + 1][3]));
                    mma_f16(Ol[hf], pa[hf], ones2);
                }
                #pragma unroll
                for (int hp = 0; hp < 4; hp++) {
                    int kv = ks * 16 + (lane & 7) + (((lane >> 3) & 1) ? 8 : 0);
                    int q  = 2 * hp + ((lane >> 4) & 1);
                    uint32_t bfr[4];
                    ldsm4t(bfr[0], bfr[1], bfr[2], bfr[3],
                           vb + kv * 128 + 16 * (q ^ (kv & 7)));
                    #pragma unroll
                    for (int hf = 0; hf < 2; hf++) {
                        mma_f16(O[hf][2 * hp],     pa[hf], &bfr[0]);
                        mma_f16(O[hf][2 * hp + 1], pa[hf], &bfr[2]);
                    }
                }
            }
        }

        #pragma unroll
        for (int hf = 0; hf < 2; hf++) {
            float l0 = __shfl_sync(0xffffffffu, Ol[hf][0], lane & 0x1C);
            float l1 = __shfl_sync(0xffffffffu, Ol[hf][2], lane & 0x1C);
            float inv0 = 1.0f / l0, inv1 = 1.0f / l1;
            unsigned short* cb0 = ctx + ((size_t)b * SEQ + row0g + hf * 16) * DIM
                                  + h * 64 + 2 * (lane & 3);
            #pragma unroll
            for (int nt = 0; nt < 8; nt++) {
                *reinterpret_cast<uint32_t*>(cb0 + nt * 8) =
                    pack_h2(O[hf][nt][0] * inv0, O[hf][nt][1] * inv0);
                *reinterpret_cast<uint32_t*>(cb0 + (size_t)8 * DIM + nt * 8) =
                    pack_h2(O[hf][nt][2] * inv1, O[hf][nt][3] * inv1);
            }
        }
    }
}

// ---------------------------------------------------------------------------
extern "C" void kernel_launch(void* const* d_in, const int* in_sizes, int n_in,
                              void* d_out, int out_size)
{
    const float* x  = (const float*)d_in[0];
    const float* Wq = (const float*)d_in[1];
    const float* bq = (const float*)d_in[2];
    const float* Wk = (const float*)d_in[3];
    const float* bk = (const float*)d_in[4];
    const float* Wv = (const float*)d_in[5];
    const float* bv = (const float*)d_in[6];
    const float* Wo = (const float*)d_in[7];
    const float* bo = (const float*)d_in[8];
    float* out = (float*)d_out;

    unsigned short *q, *k, *v, *ctx, *xr, *wt;
    cudaGetSymbolAddress((void**)&q,   g_q);
    cudaGetSymbolAddress((void**)&k,   g_k);
    cudaGetSymbolAddress((void**)&v,   g_v);
    cudaGetSymbolAddress((void**)&ctx, g_ctx);
    cudaGetSymbolAddress((void**)&xr,  g_xr);
    cudaGetSymbolAddress((void**)&wt,  g_wt);

    cudaFuncSetAttribute(gemm_mma<0>, cudaFuncAttributeMaxDynamicSharedMemorySize, GEMM_SMEM);
    cudaFuncSetAttribute(gemm_mma<1>, cudaFuncAttributeMaxDynamicSharedMemorySize, GEMM_SMEM);
    cudaFuncSetAttribute(flash_attn_mma, cudaFuncAttributeMaxDynamicSharedMemorySize, ATTN_SMEM);

    // 1. prep: input->f16 + all four W^T (one launch)
    dim3 gp(32, 32, 5), bp(32, 8);
    prep_kernel<<<gp, bp>>>(x, Wq, Wk, Wv, Wo, xr, wt);
    // 2. fused QKV projection (N = 3072), CTA 256x128, frag-pipelined
    dim3 gqkv(3 * DIM / 128, MTOT / 256);   // (24, 16)
    gemm_mma<1><<<gqkv, 256, GEMM_SMEM>>>(xr, wt, bq, bk, bv, q, k, v);
    // 3. attention (256-row CTAs, paired causal blocks)
    dim3 ga(NQB2 / 2, BATCHN * NHEAD);      // (4, 32)
    flash_attn_mma<<<ga, 256, ATTN_SMEM>>>(q, k, v, ctx);
    // 4. output projection, CTA 256x128 -> 128 CTAs (single wave)
    dim3 go(DIM / 128, MTOT / 256);         // (8, 16)
    gemm_mma<0><<<go, 256, GEMM_SMEM>>>(ctx, wt + (size_t)3 * DIM * DIM,
                                        bo, nullptr, nullptr, out, nullptr, nullptr);
}

// round 15
// speedup vs baseline: 1.0133x; 1.0067x over previous
#include <cuda_runtime.h>
#include <cuda_fp16.h>
#include <cstdint>

#define BATCHN 2
#define SEQ    2048
#define DIM    1024
#define NHEAD  16
#define HDIM   64
#define MTOT   (BATCHN*SEQ)   // 4096
#define NQB2   (SEQ/256)      // 8 attention q-blocks (256 rows each)

// ---------------- scratch (no allocs; raw u16) ----------------
__device__ unsigned short g_q[(size_t)BATCHN*NHEAD*SEQ*HDIM];   // [B,H,S,Hd] f16
__device__ unsigned short g_k[(size_t)BATCHN*NHEAD*SEQ*HDIM];
__device__ unsigned short g_v[(size_t)BATCHN*NHEAD*SEQ*HDIM];
__device__ unsigned short g_ctx[(size_t)MTOT*DIM];              // [B*S, D] f16
__device__ unsigned short g_xr[(size_t)MTOT*DIM];               // input f16
__device__ unsigned short g_wt[(size_t)4*DIM*DIM];              // W^T f16: Wq,Wk,Wv,Wo

// ---------------- helpers (compute_103-baseline PTX only) ----------------
__device__ __forceinline__ uint32_t smem_u32(const void* p) {
    uint32_t a;
    asm("{ .reg .u64 t; cvta.to.shared.u64 t, %1; cvt.u32.u64 %0, t; }" : "=r"(a) : "l"(p));
    return a;
}
__device__ __forceinline__ uint32_t pack_h2(float lo, float hi) {
    __half2 h = __floats2half2_rn(lo, hi);
    return *reinterpret_cast<uint32_t*>(&h);
}
__device__ __forceinline__ void cpasync16(uint32_t dst, const void* src) {
    asm volatile("cp.async.cg.shared.global [%0], [%1], 16;" :: "r"(dst), "l"(src));
}
#define CP_COMMIT() asm volatile("cp.async.commit_group;" ::: "memory")
#define CP_WAIT(n)  asm volatile("cp.async.wait_group %0;" :: "n"(n) : "memory")

__device__ __forceinline__ void ldsm4(uint32_t& r0, uint32_t& r1, uint32_t& r2,
                                      uint32_t& r3, uint32_t a) {
    asm volatile("ldmatrix.sync.aligned.m8n8.x4.shared.b16 {%0,%1,%2,%3}, [%4];"
                 : "=r"(r0), "=r"(r1), "=r"(r2), "=r"(r3) : "r"(a));
}
__device__ __forceinline__ void ldsm4t(uint32_t& r0, uint32_t& r1, uint32_t& r2,
                                       uint32_t& r3, uint32_t a) {
    asm volatile("ldmatrix.sync.aligned.m8n8.x4.trans.shared.b16 {%0,%1,%2,%3}, [%4];"
                 : "=r"(r0), "=r"(r1), "=r"(r2), "=r"(r3) : "r"(a));
}
// D(fp32) += A(f16 m16k16, row) * B(f16 k16n8, col)
__device__ __forceinline__ void mma_f16(float* d, const uint32_t* a, const uint32_t* b) {
    asm volatile("mma.sync.aligned.m16n8k16.row.col.f32.f16.f16.f32 "
                 "{%0,%1,%2,%3}, {%4,%5,%6,%7}, {%8,%9}, {%0,%1,%2,%3};"
                 : "+f"(d[0]), "+f"(d[1]), "+f"(d[2]), "+f"(d[3])
                 : "r"(a[0]), "r"(a[1]), "r"(a[2]), "r"(a[3]), "r"(b[0]), "r"(b[1]));
}
// D(f16x2 pair) += A * B   (f16 accumulators -- tests the half-rate theory)
__device__ __forceinline__ void mma_f16acc(uint32_t* d, const uint32_t* a, const uint32_t* b) {
    asm volatile("mma.sync.aligned.m16n8k16.row.col.f16.f16.f16.f16 "
                 "{%0,%1}, {%2,%3,%4,%5}, {%6,%7}, {%0,%1};"
                 : "+r"(d[0]), "+r"(d[1])
                 : "r"(a[0]), "r"(a[1]), "r"(a[2]), "r"(a[3]), "r"(b[0]), "r"(b[1]));
}

// ---------------------------------------------------------------------------
// prep: z<4 -> W_z^T to f16; z==4 -> input round to f16. One launch.
// ---------------------------------------------------------------------------
__global__ void prep_kernel(const float* __restrict__ x,
                            const float* __restrict__ Wq, const float* __restrict__ Wk,
                            const float* __restrict__ Wv, const float* __restrict__ Wo,
                            unsigned short* __restrict__ xr,
                            unsigned short* __restrict__ Wt) {
    int tx = threadIdx.x, ty = threadIdx.y;
    if (blockIdx.z == 4) {                  // round x -> f16 (4 float4s / thread)
        int bid = blockIdx.y * 32 + blockIdx.x;
        int t = ty * 32 + tx;
        #pragma unroll
        for (int j = 0; j < 4; j++) {
            int i = bid * 1024 + j * 256 + t;
            float4 v = reinterpret_cast<const float4*>(x)[i];
            uint2 o = { pack_h2(v.x, v.y), pack_h2(v.z, v.w) };
            reinterpret_cast<uint2*>(xr)[i] = o;
        }
        return;
    }
    __shared__ float t[32][33];
    int z = blockIdx.z;
    const float* W = (z == 0) ? Wq : (z == 1) ? Wk : (z == 2) ? Wv : Wo;
    unsigned short* dst = Wt + (size_t)z * DIM * DIM;
    int k0 = blockIdx.x * 32, n0 = blockIdx.y * 32;
    #pragma unroll
    for (int i = 0; i < 32; i += 8)
        t[ty + i][tx] = W[(size_t)(k0 + ty + i) * DIM + n0 + tx];
    __syncthreads();
    #pragma unroll
    for (int i = 0; i < 32; i += 8) {
        __half h = __float2half_rn(t[tx][ty + i]);
        dst[(size_t)(n0 + ty + i) * DIM + k0 + tx] = *reinterpret_cast<unsigned short*>(&h);
    }
}

// ---------------------------------------------------------------------------
// GEMM (mma.sync f16, fp32 accum): CTA 256x128, BK=128, 2-stage cp.async,
// fragment software pipeline. (unchanged from R14)
// MODE 0: out[4096,1024] fp32 row-major. MODE 1: fused QKV (N=3072) f16
//         scatter to [B,H,S,Hd]; segment n0>>10 selects bias/dest.
// ---------------------------------------------------------------------------
#define GEMM_SMEM 196608

template<int MODE>
__global__ void __launch_bounds__(256, 1)
gemm_mma(const unsigned short* __restrict__ A, const unsigned short* __restrict__ Wt,
         const float* __restrict__ b0p, const float* __restrict__ b1p,
         const float* __restrict__ b2p,
         void* __restrict__ o0, void* __restrict__ o1, void* __restrict__ o2)
{
    extern __shared__ char smem[];
    const uint32_t sb = smem_u32(smem);
    const int tid = threadIdx.x, lane = tid & 31, wid = tid >> 5;
    const int wm = wid >> 1, wn = wid & 1;
    const int m0 = blockIdx.y * 256, n0 = blockIdx.x * 128;

    float acc[4][8][4];
    #pragma unroll
    for (int i = 0; i < 4; i++)
        #pragma unroll
        for (int j = 0; j < 8; j++)
            #pragma unroll
            for (int r = 0; r < 4; r++) acc[i][j][r] = 0.0f;

    auto load_chunk = [&](int st, int k0) {
        uint32_t ab = sb + st * 98304, bb = ab + 65536;
        #pragma unroll
        for (int i = 0; i < 16; i++) {
            int idx = tid + i * 256, r = idx >> 4, c = idx & 15;
            cpasync16(ab + (c >> 3) * 32768 + r * 128 + 16 * ((c & 7) ^ (r & 7)),
                      A + (size_t)(m0 + r) * DIM + k0 + c * 8);
        }
        #pragma unroll
        for (int i = 0; i < 8; i++) {
            int idx = tid + i * 256, r = idx >> 4, c = idx & 15;
            cpasync16(bb + (c >> 3) * 16384 + r * 128 + 16 * ((c & 7) ^ (r & 7)),
                      Wt + (size_t)(n0 + r) * DIM + k0 + c * 8);
        }
        CP_COMMIT();
    };

    load_chunk(0, 0);
    for (int ch = 0; ch < 8; ch++) {
        int st = ch & 1;
        __syncthreads();
        if (ch + 1 < 8) { load_chunk(st ^ 1, (ch + 1) * 128); CP_WAIT(1); }
        else            { CP_WAIT(0); }
        __syncthreads();

        uint32_t ab = sb + st * 98304, bb = ab + 65536;
        uint32_t af[2][4][4], bf[2][4][4];

        auto loadA = [&](int ks, uint32_t (*a)[4]) {
            #pragma unroll
            for (int mt = 0; mt < 4; mt++) {
                int row = wm * 64 + mt * 16 + (lane & 15);
                int at  = 2 * ks + (lane >> 4);
                ldsm4(a[mt][0], a[mt][1], a[mt][2], a[mt][3],
                      ab + (at >> 3) * 32768 + row * 128 + 16 * ((at & 7) ^ (row & 7)));
            }
        };
        auto loadB = [&](int ks, uint32_t (*b)[4]) {
            #pragma unroll
            for (int pr = 0; pr < 4; pr++) {
                int row = wn * 64 + pr * 16 + (lane & 7) + ((lane & 16) ? 8 : 0);
                int at  = 2 * ks + ((lane >> 3) & 1);
                ldsm4(b[pr][0], b[pr][1], b[pr][2], b[pr][3],
                      bb + (at >> 3) * 16384 + row * 128 + 16 * ((at & 7) ^ (row & 7)));
            }
        };

        loadA(0, af[0]);
        loadB(0, bf[0]);
        #pragma unroll
        for (int ks = 0; ks < 8; ks++) {
            int cur = ks & 1;
            if (ks + 1 < 8) {
                loadA(ks + 1, af[cur ^ 1]);
                loadB(ks + 1, bf[cur ^ 1]);
            }
            #pragma unroll
            for (int mt = 0; mt < 4; mt++)
                #pragma unroll
                for (int pr = 0; pr < 4; pr++) {
                    mma_f16(acc[mt][2 * pr],     af[cur][mt], &bf[cur][pr][0]);
                    mma_f16(acc[mt][2 * pr + 1], af[cur][mt], &bf[cur][pr][2]);
                }
        }
    }

    const float* bias;
    unsigned short* outh = nullptr;
    float* outf = nullptr;
    if (MODE == 0) { bias = b0p; outf = (float*)o0; }
    else {
        int seg = n0 >> 10;
        bias = (seg == 0) ? b0p : (seg == 1) ? b1p : b2p;
        outh = (unsigned short*)((seg == 0) ? o0 : (seg == 1) ? o1 : o2);
    }
    const int rb = m0 + wm * 64 + (lane >> 2);
    const int cb = (MODE == 0 ? n0 : (n0 & 1023)) + wn * 64 + 2 * (lane & 3);
    #pragma unroll
    for (int mt = 0; mt < 4; mt++) {
        #pragma unroll
        for (int nf = 0; nf < 8; nf++) {
            int r = rb + mt * 16, c = cb + nf * 8;
            float b0 = bias[c], b1 = bias[c + 1];
            float x0 = acc[mt][nf][0] + b0, x1 = acc[mt][nf][1] + b1;
            float x2 = acc[mt][nf][2] + b0, x3 = acc[mt][nf][3] + b1;
            if (MODE == 0) {
                float2 v0 = {x0, x1}, v1 = {x2, x3};
                *reinterpret_cast<float2*>(outf + (size_t)r * DIM + c) = v0;
                *reinterpret_cast<float2*>(outf + (size_t)(r + 8) * DIM + c) = v1;
            } else {
                int bt = r >> 11, h = c >> 6, hd = c & 63;
                size_t base = (((size_t)(bt * NHEAD + h)) * SEQ) * HDIM + hd;
                *reinterpret_cast<uint32_t*>(outh + base + (size_t)(r & 2047) * HDIM) =
                    pack_h2(x0, x1);
                *reinterpret_cast<uint32_t*>(outh + base + (size_t)((r + 8) & 2047) * HDIM) =
                    pack_h2(x2, x3);
            }
        }
    }
}

// ---------------------------------------------------------------------------
// Flash attention. CTA = 256 q-rows, 8 warps x m32, kv tiles 64, 4-stage.
// NEW: QK^T uses f16 ACCUMULATORS (mma .f16.f16.f16.f16) -- 2x rate if the
// half-rate-f32-accum theory holds. Score C-frags {(r,c,c+1),(r+8,c,c+1)}
// are EXACTLY the PV A-frag layout: p_of applies in place, no pack_h2.
// Masking in packed-f16 domain (0xFC00 = -inf; ex2(-inf) = 0 exact).
// PV and l remain fp32-accum. Causal pairing + dead-tile skip unchanged.
// ---------------------------------------------------------------------------
#define ATTN_SMEM 65536

__global__ void __launch_bounds__(256, 1)
flash_attn_mma(const unsigned short* __restrict__ gq,
               const unsigned short* __restrict__ gk,
               const unsigned short* __restrict__ gv,
               unsigned short* __restrict__ ctx)
{
    extern __shared__ char smem[];
    const uint32_t sb = smem_u32(smem);
    const int tid = threadIdx.x, lane = tid & 31, wid = tid >> 5;
    const int bh = blockIdx.y, b = bh >> 4, h = bh & 15;

    const unsigned short* kbase = gk + (size_t)bh * SEQ * HDIM;
    const unsigned short* vbase = gv + (size_t)bh * SEQ * HDIM;

    const __half2 c_sc2   = __float2half2_rn(0.18033688011112042f);  // (1/8)*log2(e)
    const __half2 c_negM  = __float2half2_rn(-6.0f);
    const __half2 c_clamp = __float2half2_rn(15.0f);
    uint32_t ones2[2];
    ones2[0] = (lane < 4) ? 0x3C003C00u : 0u;   // col 0 of n8 block = 1.0
    ones2[1] = ones2[0];

    auto p_of = [&](uint32_t packed_sc) -> uint32_t {  // P = ex2(min(s*SC2-M,15))
        __half2 u = *reinterpret_cast<__half2*>(&packed_sc);
        __half2 y = __hmin2(__hfma2(u, c_sc2, c_negM), c_clamp);
        uint32_t r;
        asm("ex2.approx.f16x2 %0, %1;" : "=r"(r) : "r"(*reinterpret_cast<uint32_t*>(&y)));
        return r;
    };

    auto loadKV = [&](int t, int st) {      // K + V: 64 rows x 8 quads each
        uint32_t kb = sb + st * 16384, vb = kb + 8192;
        #pragma unroll
        for (int i = 0; i < 2; i++) {
            int idx = tid + i * 256, r = idx >> 3, c = idx & 7;
            uint32_t off = r * 128 + 16 * (c ^ (r & 7));
            const unsigned short* s = kbase + (size_t)(t * 64 + r) * 64 + c * 8;
            cpasync16(kb + off, s);
            cpasync16(vb + off, vbase + (s - kbase));
        }
        CP_COMMIT();
    };

    #pragma unroll 1
    for (int pass = 0; pass < 2; pass++) {
        const int qb = pass ? (NQB2 - 1 - blockIdx.x) : blockIdx.x;
        const int nt_tiles = 4 * qb + 4;
        const unsigned short* qg =
            gq + ((size_t)bh * SEQ + qb * 256 + wid * 32) * HDIM;

        uint32_t qf[2][4][4];
        {
            int r = lane >> 2, c2 = 2 * (lane & 3);
            #pragma unroll
            for (int hf = 0; hf < 2; hf++) {
                const unsigned short* qh = qg + hf * 16 * HDIM;
                #pragma unroll
                for (int ks = 0; ks < 4; ks++) {
                    qf[hf][ks][0] = *reinterpret_cast<const uint32_t*>(qh + r * 64 + ks * 16 + c2);
                    qf[hf][ks][1] = *reinterpret_cast<const uint32_t*>(qh + (r + 8) * 64 + ks * 16 + c2);
                    qf[hf][ks][2] = *reinterpret_cast<const uint32_t*>(qh + r * 64 + ks * 16 + 8 + c2);
                    qf[hf][ks][3] = *reinterpret_cast<const uint32_t*>(qh + (r + 8) * 64 + ks * 16 + 8 + c2);
                }
            }
        }

        float O[2][8][4];
        #pragma unroll
        for (int hf = 0; hf < 2; hf++)
            #pragma unroll
            for (int i = 0; i < 8; i++)
                #pragma unroll
                for (int j = 0; j < 4; j++) O[hf][i][j] = 0.0f;
        float Ol[2][4] = {{0,0,0,0},{0,0,0,0}};

        __syncthreads();
        loadKV(0, 0);
        loadKV(1, 1);
        loadKV(2, 2);

        const int row0g = qb * 256 + wid * 32 + (lane >> 2);

        for (int t = 0; t < nt_tiles; t++) {
            int st = t & 3;
            if (t + 2 < nt_tiles)      CP_WAIT(2);
            else if (t + 1 < nt_tiles) CP_WAIT(1);
            else                       CP_WAIT(0);
            __syncthreads();
            if (t + 3 < nt_tiles) loadKV(t + 3, (t + 3) & 3);

            const bool diag = (t >= 4 * qb);
            const int  tl   = t - 4 * qb;
            if (diag && tl * 64 > wid * 32 + 31) continue;   // P == 0, skip

            // ---- scores = Q K^T, f16 accumulators (2 regs per m16n8 tile)
            uint32_t sc2[2][8][2];
            #pragma unroll
            for (int hf = 0; hf < 2; hf++)
                #pragma unroll
                for (int i = 0; i < 8; i++) {
                    sc2[hf][i][0] = 0u; sc2[hf][i][1] = 0u;
                }

            uint32_t kb = sb + st * 16384;
            #pragma unroll
            for (int ks = 0; ks < 4; ks++) {
                #pragma unroll
                for (int pr = 0; pr < 4; pr++) {
                    int row = pr * 16 + (lane & 7) + ((lane & 16) ? 8 : 0);
                    int at  = 2 * ks + ((lane >> 3) & 1);
                    uint32_t bfr[4];
                    ldsm4(bfr[0], bfr[1], bfr[2], bfr[3],
                          kb + row * 128 + 16 * (at ^ (row & 7)));
                    #pragma unroll
                    for (int hf = 0; hf < 2; hf++) {
                        mma_f16acc(sc2[hf][2 * pr],     qf[hf][ks], &bfr[0]);
                        mma_f16acc(sc2[hf][2 * pr + 1], qf[hf][ks], &bfr[2]);
                    }
                }
            }

            // ---- causal mask in packed-f16 domain (diag tiles only)
            if (diag && tl * 64 + 63 > wid * 32) {
                #pragma unroll
                for (int hf = 0; hf < 2; hf++) {
                    int r0 = row0g + hf * 16;           // row of reg0; reg1 = r0+8
                    #pragma unroll
                    for (int nt = 0; nt < 8; nt++) {
                        int col = t * 64 + nt * 8 + 2 * (lane & 3);
                        uint32_t s0 = sc2[hf][nt][0];
                        if (col > r0)          s0 = 0xFC00FC00u;
                        else if (col + 1 > r0) s0 = (s0 & 0xFFFFu) | 0xFC000000u;
                        sc2[hf][nt][0] = s0;
                        uint32_t s1 = sc2[hf][nt][1];
                        if (col > r0 + 8)          s1 = 0xFC00FC00u;
                        else if (col + 1 > r0 + 8) s1 = (s1 & 0xFFFFu) | 0xFC000000u;
                        sc2[hf][nt][1] = s1;
                    }
                }
            }

            // ---- O += P V (+ ones col -> l); P directly from score regs
            uint32_t vb = sb + st * 16384 + 8192;
            #pragma unroll
            for (int ks = 0; ks < 4; ks++) {
                uint32_t pa[2][4];
                #pragma unroll
                for (int hf = 0; hf < 2; hf++) {
                    pa[hf][0] = p_of(sc2[hf][2 * ks][0]);
                    pa[hf][1] = p_of(sc2[hf][2 * ks][1]);
                    pa[hf][2] = p_of(sc2[hf][2 * ks + 1][0]);
                    pa[hf][3] = p_of(sc2[hf][2 * ks + 1][1]);
                    mma_f16(Ol[hf], pa[hf], ones2);
                }
                #pragma unroll
                for (int hp = 0; hp < 4; hp++) {
                    int kv = ks * 16 + (lane & 7) + (((lane >> 3) & 1) ? 8 : 0);
                    int q  = 2 * hp + ((lane >> 4) & 1);
                    uint32_t bfr[4];
                    ldsm4t(bfr[0], bfr[1], bfr[2], bfr[3],
                           vb + kv * 128 + 16 * (q ^ (kv & 7)));
                    #pragma unroll
                    for (int hf = 0; hf < 2; hf++) {
                        mma_f16(O[hf][2 * hp],     pa[hf], &bfr[0]);
                        mma_f16(O[hf][2 * hp + 1], pa[hf], &bfr[2]);
                    }
                }
            }
        }

        #pragma unroll
        for (int hf = 0; hf < 2; hf++) {
            float l0 = __shfl_sync(0xffffffffu, Ol[hf][0], lane & 0x1C);
            float l1 = __shfl_sync(0xffffffffu, Ol[hf][2], lane & 0x1C);
            float inv0 = 1.0f / l0, inv1 = 1.0f / l1;
            unsigned short* cb0 = ctx + ((size_t)b * SEQ + row0g + hf * 16) * DIM
                                  + h * 64 + 2 * (lane & 3);
            #pragma unroll
            for (int nt = 0; nt < 8; nt++) {
                *reinterpret_cast<uint32_t*>(cb0 + nt * 8) =
                    pack_h2(O[hf][nt][0] * inv0, O[hf][nt][1] * inv0);
                *reinterpret_cast<uint32_t*>(cb0 + (size_t)8 * DIM + nt * 8) =
                    pack_h2(O[hf][nt][2] * inv1, O[hf][nt][3] * inv1);
            }
        }
    }
}

// ---------------------------------------------------------------------------
extern "C" void kernel_launch(void* const* d_in, const int* in_sizes, int n_in,
                              void* d_out, int out_size)
{
    const float* x  = (const float*)d_in[0];
    const float* Wq = (const float*)d_in[1];
    const float* bq = (const float*)d_in[2];
    const float* Wk = (const float*)d_in[3];
    const float* bk = (const float*)d_in[4];
    const float* Wv = (const float*)d_in[5];
    const float* bv = (const float*)d_in[6];
    const float* Wo = (const float*)d_in[7];
    const float* bo = (const float*)d_in[8];
    float* out = (float*)d_out;

    unsigned short *q, *k, *v, *ctx, *xr, *wt;
    cudaGetSymbolAddress((void**)&q,   g_q);
    cudaGetSymbolAddress((void**)&k,   g_k);
    cudaGetSymbolAddress((void**)&v,   g_v);
    cudaGetSymbolAddress((void**)&ctx, g_ctx);
    cudaGetSymbolAddress((void**)&xr,  g_xr);
    cudaGetSymbolAddress((void**)&wt,  g_wt);

    cudaFuncSetAttribute(gemm_mma<0>, cudaFuncAttributeMaxDynamicSharedMemorySize, GEMM_SMEM);
    cudaFuncSetAttribute(gemm_mma<1>, cudaFuncAttributeMaxDynamicSharedMemorySize, GEMM_SMEM);
    cudaFuncSetAttribute(flash_attn_mma, cudaFuncAttributeMaxDynamicSharedMemorySize, ATTN_SMEM);

    // 1. prep: input->f16 + all four W^T (one launch)
    dim3 gp(32, 32, 5), bp(32, 8);
    prep_kernel<<<gp, bp>>>(x, Wq, Wk, Wv, Wo, xr, wt);
    // 2. fused QKV projection (N = 3072), CTA 256x128, frag-pipelined
    dim3 gqkv(3 * DIM / 128, MTOT / 256);   // (24, 16)
    gemm_mma<1><<<gqkv, 256, GEMM_SMEM>>>(xr, wt, bq, bk, bv, q, k, v);
    // 3. attention (256-row CTAs, paired causal blocks, f16-accum QK^T)
    dim3 ga(NQB2 / 2, BATCHN * NHEAD);      // (4, 32)
    flash_attn_mma<<<ga, 256, ATTN_SMEM>>>(q, k, v, ctx);
    // 4. output projection, CTA 256x128 -> 128 CTAs (single wave)
    dim3 go(DIM / 128, MTOT / 256);         // (8, 16)
    gemm_mma<0><<<go, 256, GEMM_SMEM>>>(ctx, wt + (size_t)3 * DIM * DIM,
                                        bo, nullptr, nullptr, out, nullptr, nullptr);
}

// round 16
// speedup vs baseline: 1.0269x; 1.0135x over previous
#include <cuda_runtime.h>
#include <cuda_fp16.h>
#include <cstdint>

#define BATCHN 2
#define SEQ    2048
#define DIM    1024
#define NHEAD  16
#define HDIM   64
#define MTOT   (BATCHN*SEQ)   // 4096
#define NQB2   (SEQ/256)      // 8 attention q-blocks (256 rows each)

// ---------------- scratch (no allocs; raw u16) ----------------
__device__ unsigned short g_q[(size_t)BATCHN*NHEAD*SEQ*HDIM];   // [B,H,S,Hd] f16
__device__ unsigned short g_k[(size_t)BATCHN*NHEAD*SEQ*HDIM];
__device__ unsigned short g_v[(size_t)BATCHN*NHEAD*SEQ*HDIM];
__device__ unsigned short g_ctx[(size_t)MTOT*DIM];              // [B*S, D] f16
__device__ unsigned short g_xr[(size_t)MTOT*DIM];               // input f16
__device__ unsigned short g_wt[(size_t)4*DIM*DIM];              // W^T f16: Wq,Wk,Wv,Wo

// ---------------- helpers (compute_103-baseline PTX only) ----------------
__device__ __forceinline__ uint32_t smem_u32(const void* p) {
    uint32_t a;
    asm("{ .reg .u64 t; cvta.to.shared.u64 t, %1; cvt.u32.u64 %0, t; }" : "=r"(a) : "l"(p));
    return a;
}
__device__ __forceinline__ uint32_t pack_h2(float lo, float hi) {
    __half2 h = __floats2half2_rn(lo, hi);
    return *reinterpret_cast<uint32_t*>(&h);
}
__device__ __forceinline__ void cpasync16(uint32_t dst, const void* src) {
    asm volatile("cp.async.cg.shared.global [%0], [%1], 16;" :: "r"(dst), "l"(src));
}
#define CP_COMMIT() asm volatile("cp.async.commit_group;" ::: "memory")
#define CP_WAIT(n)  asm volatile("cp.async.wait_group %0;" :: "n"(n) : "memory")

__device__ __forceinline__ void ldsm4(uint32_t& r0, uint32_t& r1, uint32_t& r2,
                                      uint32_t& r3, uint32_t a) {
    asm volatile("ldmatrix.sync.aligned.m8n8.x4.shared.b16 {%0,%1,%2,%3}, [%4];"
                 : "=r"(r0), "=r"(r1), "=r"(r2), "=r"(r3) : "r"(a));
}
__device__ __forceinline__ void ldsm4t(uint32_t& r0, uint32_t& r1, uint32_t& r2,
                                       uint32_t& r3, uint32_t a) {
    asm volatile("ldmatrix.sync.aligned.m8n8.x4.trans.shared.b16 {%0,%1,%2,%3}, [%4];"
                 : "=r"(r0), "=r"(r1), "=r"(r2), "=r"(r3) : "r"(a));
}
// D(fp32) += A(f16 m16k16, row) * B(f16 k16n8, col)
__device__ __forceinline__ void mma_f16(float* d, const uint32_t* a, const uint32_t* b) {
    asm volatile("mma.sync.aligned.m16n8k16.row.col.f32.f16.f16.f32 "
                 "{%0,%1,%2,%3}, {%4,%5,%6,%7}, {%8,%9}, {%0,%1,%2,%3};"
                 : "+f"(d[0]), "+f"(d[1]), "+f"(d[2]), "+f"(d[3])
                 : "r"(a[0]), "r"(a[1]), "r"(a[2]), "r"(a[3]), "r"(b[0]), "r"(b[1]));
}
// D(f16x2 pair) += A * B   (f16 accumulators; C-frag == PV A-frag layout)
__device__ __forceinline__ void mma_f16acc(uint32_t* d, const uint32_t* a, const uint32_t* b) {
    asm volatile("mma.sync.aligned.m16n8k16.row.col.f16.f16.f16.f16 "
                 "{%0,%1}, {%2,%3,%4,%5}, {%6,%7}, {%0,%1};"
                 : "+r"(d[0]), "+r"(d[1])
                 : "r"(a[0]), "r"(a[1]), "r"(a[2]), "r"(a[3]), "r"(b[0]), "r"(b[1]));
}

// ---------------------------------------------------------------------------
// prep: z<4 -> W_z^T to f16; z==4 -> input round to f16. One launch.
// ---------------------------------------------------------------------------
__global__ void prep_kernel(const float* __restrict__ x,
                            const float* __restrict__ Wq, const float* __restrict__ Wk,
                            const float* __restrict__ Wv, const float* __restrict__ Wo,
                            unsigned short* __restrict__ xr,
                            unsigned short* __restrict__ Wt) {
    int tx = threadIdx.x, ty = threadIdx.y;
    if (blockIdx.z == 4) {                  // round x -> f16 (4 float4s / thread)
        int bid = blockIdx.y * 32 + blockIdx.x;
        int t = ty * 32 + tx;
        #pragma unroll
        for (int j = 0; j < 4; j++) {
            int i = bid * 1024 + j * 256 + t;
            float4 v = reinterpret_cast<const float4*>(x)[i];
            uint2 o = { pack_h2(v.x, v.y), pack_h2(v.z, v.w) };
            reinterpret_cast<uint2*>(xr)[i] = o;
        }
        return;
    }
    __shared__ float t[32][33];
    int z = blockIdx.z;
    const float* W = (z == 0) ? Wq : (z == 1) ? Wk : (z == 2) ? Wv : Wo;
    unsigned short* dst = Wt + (size_t)z * DIM * DIM;
    int k0 = blockIdx.x * 32, n0 = blockIdx.y * 32;
    #pragma unroll
    for (int i = 0; i < 32; i += 8)
        t[ty + i][tx] = W[(size_t)(k0 + ty + i) * DIM + n0 + tx];
    __syncthreads();
    #pragma unroll
    for (int i = 0; i < 32; i += 8) {
        __half h = __float2half_rn(t[tx][ty + i]);
        dst[(size_t)(n0 + ty + i) * DIM + k0 + tx] = *reinterpret_cast<unsigned short*>(&h);
    }
}

// ---------------------------------------------------------------------------
// GEMM (mma.sync f16, fp32 accum): CTA 256x128, BK=128, 2-stage cp.async,
// fragment software pipeline. (unchanged from R14 -- at mma.sync floor)
// MODE 0: out[4096,1024] fp32 row-major. MODE 1: fused QKV (N=3072) f16
//         scatter to [B,H,S,Hd]; segment n0>>10 selects bias/dest.
// ---------------------------------------------------------------------------
#define GEMM_SMEM 196608

template<int MODE>
__global__ void __launch_bounds__(256, 1)
gemm_mma(const unsigned short* __restrict__ A, const unsigned short* __restrict__ Wt,
         const float* __restrict__ b0p, const float* __restrict__ b1p,
         const float* __restrict__ b2p,
         void* __restrict__ o0, void* __restrict__ o1, void* __restrict__ o2)
{
    extern __shared__ char smem[];
    const uint32_t sb = smem_u32(smem);
    const int tid = threadIdx.x, lane = tid & 31, wid = tid >> 5;
    const int wm = wid >> 1, wn = wid & 1;
    const int m0 = blockIdx.y * 256, n0 = blockIdx.x * 128;

    float acc[4][8][4];
    #pragma unroll
    for (int i = 0; i < 4; i++)
        #pragma unroll
        for (int j = 0; j < 8; j++)
            #pragma unroll
            for (int r = 0; r < 4; r++) acc[i][j][r] = 0.0f;

    auto load_chunk = [&](int st, int k0) {
        uint32_t ab = sb + st * 98304, bb = ab + 65536;
        #pragma unroll
        for (int i = 0; i < 16; i++) {
            int idx = tid + i * 256, r = idx >> 4, c = idx & 15;
            cpasync16(ab + (c >> 3) * 32768 + r * 128 + 16 * ((c & 7) ^ (r & 7)),
                      A + (size_t)(m0 + r) * DIM + k0 + c * 8);
        }
        #pragma unroll
        for (int i = 0; i < 8; i++) {
            int idx = tid + i * 256, r = idx >> 4, c = idx & 15;
            cpasync16(bb + (c >> 3) * 16384 + r * 128 + 16 * ((c & 7) ^ (r & 7)),
                      Wt + (size_t)(n0 + r) * DIM + k0 + c * 8);
        }
        CP_COMMIT();
    };

    load_chunk(0, 0);
    for (int ch = 0; ch < 8; ch++) {
        int st = ch & 1;
        __syncthreads();
        if (ch + 1 < 8) { load_chunk(st ^ 1, (ch + 1) * 128); CP_WAIT(1); }
        else            { CP_WAIT(0); }
        __syncthreads();

        uint32_t ab = sb + st * 98304, bb = ab + 65536;
        uint32_t af[2][4][4], bf[2][4][4];

        auto loadA = [&](int ks, uint32_t (*a)[4]) {
            #pragma unroll
            for (int mt = 0; mt < 4; mt++) {
                int row = wm * 64 + mt * 16 + (lane & 15);
                int at  = 2 * ks + (lane >> 4);
                ldsm4(a[mt][0], a[mt][1], a[mt][2], a[mt][3],
                      ab + (at >> 3) * 32768 + row * 128 + 16 * ((at & 7) ^ (row & 7)));
            }
        };
        auto loadB = [&](int ks, uint32_t (*b)[4]) {
            #pragma unroll
            for (int pr = 0; pr < 4; pr++) {
                int row = wn * 64 + pr * 16 + (lane & 7) + ((lane & 16) ? 8 : 0);
                int at  = 2 * ks + ((lane >> 3) & 1);
                ldsm4(b[pr][0], b[pr][1], b[pr][2], b[pr][3],
                      bb + (at >> 3) * 16384 + row * 128 + 16 * ((at & 7) ^ (row & 7)));
            }
        };

        loadA(0, af[0]);
        loadB(0, bf[0]);
        #pragma unroll
        for (int ks = 0; ks < 8; ks++) {
            int cur = ks & 1;
            if (ks + 1 < 8) {
                loadA(ks + 1, af[cur ^ 1]);
                loadB(ks + 1, bf[cur ^ 1]);
            }
            #pragma unroll
            for (int mt = 0; mt < 4; mt++)
                #pragma unroll
                for (int pr = 0; pr < 4; pr++) {
                    mma_f16(acc[mt][2 * pr],     af[cur][mt], &bf[cur][pr][0]);
                    mma_f16(acc[mt][2 * pr + 1], af[cur][mt], &bf[cur][pr][2]);
                }
        }
    }

    const float* bias;
    unsigned short* outh = nullptr;
    float* outf = nullptr;
    if (MODE == 0) { bias = b0p; outf = (float*)o0; }
    else {
        int seg = n0 >> 10;
        bias = (seg == 0) ? b0p : (seg == 1) ? b1p : b2p;
        outh = (unsigned short*)((seg == 0) ? o0 : (seg == 1) ? o1 : o2);
    }
    const int rb = m0 + wm * 64 + (lane >> 2);
    const int cb = (MODE == 0 ? n0 : (n0 & 1023)) + wn * 64 + 2 * (lane & 3);
    #pragma unroll
    for (int mt = 0; mt < 4; mt++) {
        #pragma unroll
        for (int nf = 0; nf < 8; nf++) {
            int r = rb + mt * 16, c = cb + nf * 8;
            float b0 = bias[c], b1 = bias[c + 1];
            float x0 = acc[mt][nf][0] + b0, x1 = acc[mt][nf][1] + b1;
            float x2 = acc[mt][nf][2] + b0, x3 = acc[mt][nf][3] + b1;
            if (MODE == 0) {
                float2 v0 = {x0, x1}, v1 = {x2, x3};
                *reinterpret_cast<float2*>(outf + (size_t)r * DIM + c) = v0;
                *reinterpret_cast<float2*>(outf + (size_t)(r + 8) * DIM + c) = v1;
            } else {
                int bt = r >> 11, h = c >> 6, hd = c & 63;
                size_t base = (((size_t)(bt * NHEAD + h)) * SEQ) * HDIM + hd;
                *reinterpret_cast<uint32_t*>(outh + base + (size_t)(r & 2047) * HDIM) =
                    pack_h2(x0, x1);
                *reinterpret_cast<uint32_t*>(outh + base + (size_t)((r + 8) & 2047) * HDIM) =
                    pack_h2(x2, x3);
            }
        }
    }
}

// ---------------------------------------------------------------------------
// Flash attention. CTA = 256 q-rows, 8 warps x m32. f16-accum QK^T (R15).
// NEW: kv pipelined in 128-wide CHUNKS, 4 stages x 32KB = 128KB smem ->
// ONE CP_WAIT + ONE __syncthreads per 128 kv cols (half the sync events).
// Each chunk = two 64-wide sub-tiles processed back-to-back (identical math
// and order to R15 -> bit-identical output). Causal pairing + warp-level
// dead-sub-tile skip unchanged.
// smem: stage st at st*32768 (K 16KB, V 16KB at +16384).
// ---------------------------------------------------------------------------
#define ATTN_SMEM 131072

__global__ void __launch_bounds__(256, 1)
flash_attn_mma(const unsigned short* __restrict__ gq,
               const unsigned short* __restrict__ gk,
               const unsigned short* __restrict__ gv,
               unsigned short* __restrict__ ctx)
{
    extern __shared__ char smem[];
    const uint32_t sb = smem_u32(smem);
    const int tid = threadIdx.x, lane = tid & 31, wid = tid >> 5;
    const int bh = blockIdx.y, b = bh >> 4, h = bh & 15;

    const unsigned short* kbase = gk + (size_t)bh * SEQ * HDIM;
    const unsigned short* vbase = gv + (size_t)bh * SEQ * HDIM;

    const __half2 c_sc2   = __float2half2_rn(0.18033688011112042f);  // (1/8)*log2(e)
    const __half2 c_negM  = __float2half2_rn(-6.0f);
    const __half2 c_clamp = __float2half2_rn(15.0f);
    uint32_t ones2[2];
    ones2[0] = (lane < 4) ? 0x3C003C00u : 0u;   // col 0 of n8 block = 1.0
    ones2[1] = ones2[0];

    auto p_of = [&](uint32_t packed_sc) -> uint32_t {  // P = ex2(min(s*SC2-M,15))
        __half2 u = *reinterpret_cast<__half2*>(&packed_sc);
        __half2 y = __hmin2(__hfma2(u, c_sc2, c_negM), c_clamp);
        uint32_t r;
        asm("ex2.approx.f16x2 %0, %1;" : "=r"(r) : "r"(*reinterpret_cast<uint32_t*>(&y)));
        return r;
    };

    // one 128-row kv chunk (K + V), stage st in [0,4)
    auto loadKV = [&](int t2, int st) {
        uint32_t kb = sb + st * 32768, vb = kb + 16384;
        #pragma unroll
        for (int i = 0; i < 4; i++) {
            int idx = tid + i * 256, r = idx >> 3, c = idx & 7;
            uint32_t off = r * 128 + 16 * (c ^ (r & 7));
            const unsigned short* s = kbase + (size_t)(t2 * 128 + r) * 64 + c * 8;
            cpasync16(kb + off, s);
            cpasync16(vb + off, vbase + (s - kbase));
        }
        CP_COMMIT();
    };

    #pragma unroll 1
    for (int pass = 0; pass < 2; pass++) {
        const int qb = pass ? (NQB2 - 1 - blockIdx.x) : blockIdx.x;
        const int nt2 = 2 * qb + 2;             // 128-wide chunks
        const unsigned short* qg =
            gq + ((size_t)bh * SEQ + qb * 256 + wid * 32) * HDIM;

        uint32_t qf[2][4][4];
        {
            int r = lane >> 2, c2 = 2 * (lane & 3);
            #pragma unroll
            for (int hf = 0; hf < 2; hf++) {
                const unsigned short* qh = qg + hf * 16 * HDIM;
                #pragma unroll
                for (int ks = 0; ks < 4; ks++) {
                    qf[hf][ks][0] = *reinterpret_cast<const uint32_t*>(qh + r * 64 + ks * 16 + c2);
                    qf[hf][ks][1] = *reinterpret_cast<const uint32_t*>(qh + (r + 8) * 64 + ks * 16 + c2);
                    qf[hf][ks][2] = *reinterpret_cast<const uint32_t*>(qh + r * 64 + ks * 16 + 8 + c2);
                    qf[hf][ks][3] = *reinterpret_cast<const uint32_t*>(qh + (r + 8) * 64 + ks * 16 + 8 + c2);
                }
            }
        }

        float O[2][8][4];
        #pragma unroll
        for (int hf = 0; hf < 2; hf++)
            #pragma unroll
            for (int i = 0; i < 8; i++)
                #pragma unroll
                for (int j = 0; j < 4; j++) O[hf][i][j] = 0.0f;
        float Ol[2][4] = {{0,0,0,0},{0,0,0,0}};

        __syncthreads();                        // smem reuse across passes
        loadKV(0, 0);
        if (nt2 > 1) loadKV(1, 1);
        if (nt2 > 2) loadKV(2, 2);

        const int row0g = qb * 256 + wid * 32 + (lane >> 2);

        for (int t2 = 0; t2 < nt2; t2++) {
            int st = t2 & 3;
            if (t2 + 2 < nt2)      CP_WAIT(2);
            else if (t2 + 1 < nt2) CP_WAIT(1);
            else                   CP_WAIT(0);
            __syncthreads();                    // chunk t2 visible; t2-1 consumed
            if (t2 + 3 < nt2) loadKV(t2 + 3, (t2 + 3) & 3);

            #pragma unroll
            for (int s = 0; s < 2; s++) {       // two 64-wide sub-tiles
                const int t = 2 * t2 + s;       // global 64-tile index
                const bool diag = (t >= 4 * qb);
                const int  tl   = t - 4 * qb;
                if (diag && tl * 64 > wid * 32 + 31) continue;   // P==0, skip

                // ---- scores = Q K^T, f16 accumulators
                uint32_t sc2[2][8][2];
                #pragma unroll
                for (int hf = 0; hf < 2; hf++)
                    #pragma unroll
                    for (int i = 0; i < 8; i++) {
                        sc2[hf][i][0] = 0u; sc2[hf][i][1] = 0u;
                    }

                uint32_t kb = sb + st * 32768 + s * 8192;
                #pragma unroll
                for (int ks = 0; ks < 4; ks++) {
                    #pragma unroll
                    for (int pr = 0; pr < 4; pr++) {
                        int row = pr * 16 + (lane & 7) + ((lane & 16) ? 8 : 0);
                        int at  = 2 * ks + ((lane >> 3) & 1);
                        uint32_t bfr[4];
                        ldsm4(bfr[0], bfr[1], bfr[2], bfr[3],
                              kb + row * 128 + 16 * (at ^ (row & 7)));
                        #pragma unroll
                        for (int hf = 0; hf < 2; hf++) {
                            mma_f16acc(sc2[hf][2 * pr],     qf[hf][ks], &bfr[0]);
                            mma_f16acc(sc2[hf][2 * pr + 1], qf[hf][ks], &bfr[2]);
                        }
                    }
                }

                // ---- causal mask in packed-f16 domain (diag tiles only)
                if (diag && tl * 64 + 63 > wid * 32) {
                    #pragma unroll
                    for (int hf = 0; hf < 2; hf++) {
                        int r0 = row0g + hf * 16;
                        #pragma unroll
                        for (int nt = 0; nt < 8; nt++) {
                            int col = t * 64 + nt * 8 + 2 * (lane & 3);
                            uint32_t s0 = sc2[hf][nt][0];
                            if (col > r0)          s0 = 0xFC00FC00u;
                            else if (col + 1 > r0) s0 = (s0 & 0xFFFFu) | 0xFC000000u;
                            sc2[hf][nt][0] = s0;
                            uint32_t s1 = sc2[hf][nt][1];
                            if (col > r0 + 8)          s1 = 0xFC00FC00u;
                            else if (col + 1 > r0 + 8) s1 = (s1 & 0xFFFFu) | 0xFC000000u;
                            sc2[hf][nt][1] = s1;
                        }
                    }
                }

                // ---- O += P V (+ ones col -> l); P direct from score regs
                uint32_t vb = sb + st * 32768 + 16384 + s * 8192;
                #pragma unroll
                for (int ks = 0; ks < 4; ks++) {
                    uint32_t pa[2][4];
                    #pragma unroll
                    for (int hf = 0; hf < 2; hf++) {
                        pa[hf][0] = p_of(sc2[hf][2 * ks][0]);
                        pa[hf][1] = p_of(sc2[hf][2 * ks][1]);
                        pa[hf][2] = p_of(sc2[hf][2 * ks + 1][0]);
                        pa[hf][3] = p_of(sc2[hf][2 * ks + 1][1]);
                        mma_f16(Ol[hf], pa[hf], ones2);
                    }
                    #pragma unroll
                    for (int hp = 0; hp < 4; hp++) {
                        int kv = ks * 16 + (lane & 7) + (((lane >> 3) & 1) ? 8 : 0);
                        int q  = 2 * hp + ((lane >> 4) & 1);
                        uint32_t bfr[4];
                        ldsm4t(bfr[0], bfr[1], bfr[2], bfr[3],
                               vb + kv * 128 + 16 * (q ^ (kv & 7)));
                        #pragma unroll
                        for (int hf = 0; hf < 2; hf++) {
                            mma_f16(O[hf][2 * hp],     pa[hf], &bfr[0]);
                            mma_f16(O[hf][2 * hp + 1], pa[hf], &bfr[2]);
                        }
                    }
                }
            }
        }

        #pragma unroll
        for (int hf = 0; hf < 2; hf++) {
            float l0 = __shfl_sync(0xffffffffu, Ol[hf][0], lane & 0x1C);
            float l1 = __shfl_sync(0xffffffffu, Ol[hf][2], lane & 0x1C);
            float inv0 = 1.0f / l0, inv1 = 1.0f / l1;
            unsigned short* cb0 = ctx + ((size_t)b * SEQ + row0g + hf * 16) * DIM
                                  + h * 64 + 2 * (lane & 3);
            #pragma unroll
            for (int nt = 0; nt < 8; nt++) {
                *reinterpret_cast<uint32_t*>(cb0 + nt * 8) =
                    pack_h2(O[hf][nt][0] * inv0, O[hf][nt][1] * inv0);
                *reinterpret_cast<uint32_t*>(cb0 + (size_t)8 * DIM + nt * 8) =
                    pack_h2(O[hf][nt][2] * inv1, O[hf][nt][3] * inv1);
            }
        }
    }
}

// ---------------------------------------------------------------------------
extern "C" void kernel_launch(void* const* d_in, const int* in_sizes, int n_in,
                              void* d_out, int out_size)
{
    const float* x  = (const float*)d_in[0];
    const float* Wq = (const float*)d_in[1];
    const float* bq = (const float*)d_in[2];
    const float* Wk = (const float*)d_in[3];
    const float* bk = (const float*)d_in[4];
    const float* Wv = (const float*)d_in[5];
    const float* bv = (const float*)d_in[6];
    const float* Wo = (const float*)d_in[7];
    const float* bo = (const float*)d_in[8];
    float* out = (float*)d_out;

    unsigned short *q, *k, *v, *ctx, *xr, *wt;
    cudaGetSymbolAddress((void**)&q,   g_q);
    cudaGetSymbolAddress((void**)&k,   g_k);
    cudaGetSymbolAddress((void**)&v,   g_v);
    cudaGetSymbolAddress((void**)&ctx, g_ctx);
    cudaGetSymbolAddress((void**)&xr,  g_xr);
    cudaGetSymbolAddress((void**)&wt,  g_wt);

    cudaFuncSetAttribute(gemm_mma<0>, cudaFuncAttributeMaxDynamicSharedMemorySize, GEMM_SMEM);
    cudaFuncSetAttribute(gemm_mma<1>, cudaFuncAttributeMaxDynamicSharedMemorySize, GEMM_SMEM);
    cudaFuncSetAttribute(flash_attn_mma, cudaFuncAttributeMaxDynamicSharedMemorySize, ATTN_SMEM);

    // 1. prep: input->f16 + all four W^T (one launch)
    dim3 gp(32, 32, 5), bp(32, 8);
    prep_kernel<<<gp, bp>>>(x, Wq, Wk, Wv, Wo, xr, wt);
    // 2. fused QKV projection (N = 3072), CTA 256x128, frag-pipelined
    dim3 gqkv(3 * DIM / 128, MTOT / 256);   // (24, 16)
    gemm_mma<1><<<gqkv, 256, GEMM_SMEM>>>(xr, wt, bq, bk, bv, q, k, v);
    // 3. attention (256-row CTAs, paired causal blocks, 128-wide kv chunks)
    dim3 ga(NQB2 / 2, BATCHN * NHEAD);      // (4, 32)
    flash_attn_mma<<<ga, 256, ATTN_SMEM>>>(q, k, v, ctx);
    // 4. output projection, CTA 256x128 -> 128 CTAs (single wave)
    dim3 go(DIM / 128, MTOT / 256);         // (8, 16)
    gemm_mma<0><<<go, 256, GEMM_SMEM>>>(ctx, wt + (size_t)3 * DIM * DIM,
                                        bo, nullptr, nullptr, out, nullptr, nullptr);
}